// round 13
// baseline (speedup 1.0000x reference)
#include <cuda_runtime.h>
#include <cuda_fp16.h>
#include <math.h>
#include <stdint.h>

#define DN    512
#define DQv   256
#define NPG   4096
#define NB    64
#define MI    8
#define NTOT  (NB*NPG)
#define KSEL  1229           // ceil(0.3 * 4096)

#define BM   128
#define BN   128
#define BK   64
#define NSTG (DN/BK)         // 8

// ---------------- scratch ----------------
__device__ float g_s0[NB * MI * NPG];     // scores partial, col-half 0 (8 MB)
__device__ float g_s1[NB * MI * NPG];     // col-half 1
__device__ __half g_Whi[DN * DQv];        // W*512 split hi
__device__ __half g_Wlo[DN * DQv];        // W*512 split lo

// ---------------- smem layout (bytes) ----------------
#define A_PADH 72     // halves per A row (64 data + 8 pad); 144B = 9x16B (odd)
#define B_PADH 136    // halves per B row (128 data + 8 pad); 272B = 17x16B (odd)
#define A_STG  18432  // 128 x 144B
#define B_STG  17408  // 64 x 272B
#define SM_AHI 0                       // 2 x 18432
#define SM_ALO 36864                   // 2 x 18432
#define SM_BHI 73728                   // 2 x 17408
#define SM_BLO 108544                  // 2 x 17408
#define SM_US  143360                  // 8*128 floats = 4096
#define SM_BNv 147456                  // 128 floats = 512
#define SM_DYN 147968

__device__ __forceinline__ uint32_t smem_u32(const void* p) {
    uint32_t a;
    asm("{ .reg .u64 t; cvta.to.shared.u64 t, %1; cvt.u32.u64 %0, t; }"
        : "=r"(a) : "l"(p));
    return a;
}

#define LDSM4(r, addr) \
    asm volatile("ldmatrix.sync.aligned.m8n8.x4.shared.b16 {%0,%1,%2,%3}, [%4];" \
        : "=r"((r)[0]), "=r"((r)[1]), "=r"((r)[2]), "=r"((r)[3]) : "r"(addr))

#define LDSM4T(r, addr) \
    asm volatile("ldmatrix.sync.aligned.m8n8.x4.trans.shared.b16 {%0,%1,%2,%3}, [%4];" \
        : "=r"((r)[0]), "=r"((r)[1]), "=r"((r)[2]), "=r"((r)[3]) : "r"(addr))

// fp32-accumulate MMA (main term)
#define MMA16816(c, a, b0, b1) \
    asm volatile("mma.sync.aligned.m16n8k16.row.col.f32.f16.f16.f32 " \
        "{%0,%1,%2,%3}, {%4,%5,%6,%7}, {%8,%9}, {%0,%1,%2,%3};" \
        : "+f"((c)[0]), "+f"((c)[1]), "+f"((c)[2]), "+f"((c)[3]) \
        : "r"((a)[0]), "r"((a)[1]), "r"((a)[2]), "r"((a)[3]), "r"(b0), "r"(b1))

// fp16-accumulate MMA (correction terms; proven rel_err 0.0 in round 11)
#define MMA16816H(c, a, b0, b1) \
    asm volatile("mma.sync.aligned.m16n8k16.row.col.f16.f16.f16.f16 " \
        "{%0,%1}, {%2,%3,%4,%5}, {%6,%7}, {%0,%1};" \
        : "+r"((c)[0]), "+r"((c)[1]) \
        : "r"((a)[0]), "r"((a)[1]), "r"((a)[2]), "r"((a)[3]), "r"(b0), "r"(b1))

#define CPASYNC16(dst, src) \
    asm volatile("cp.async.ca.shared.global [%0], [%1], 16;" \
        :: "r"(dst), "l"(src) : "memory")
#define CPASYNC_COMMIT() asm volatile("cp.async.commit_group;" ::: "memory")
#define CPASYNC_WAIT0()  asm volatile("cp.async.wait_group 0;" ::: "memory")

// ---------------------------------------------------------------------------
// Prologue: W [512][256] fp32 -> fp16 Dekker split of W*512 (exact residual)
// ---------------------------------------------------------------------------
__global__ void convert_w(const float* __restrict__ Wn) {
    int idx = blockIdx.x * 256 + threadIdx.x;     // 0..131071
    float w = Wn[idx] * 512.0f;
    __half hi = __float2half_rn(w);
    __half lo = __float2half_rn(w - __half2float(hi));
    g_Whi[idx] = hi;
    g_Wlo[idx] = lo;
}

// ---------------------------------------------------------------------------
// Main: h = gelu((x@Wn)+bn) fused with partial scores over this block's 128
// cols. fp16 2-split 3-term: xh*wh fp32acc, corrections fp16acc.
// grid = (2048, 2). BK=64 (8 stages; half the barrier overhead of BK=32).
// ---------------------------------------------------------------------------
__global__ void __launch_bounds__(256)
gemm_hmma(const float* __restrict__ x, const float* __restrict__ u,
          const float* __restrict__ bn)
{
    extern __shared__ char smem[];
    const uint32_t sb = smem_u32(smem);
    const int tid  = threadIdx.x;
    const int wid  = tid >> 5, lane = tid & 31;
    const int wm   = wid & 3, wn = wid >> 2;     // warp grid 4(M) x 2(N)
    const int rowBase = blockIdx.x * BM;
    const int colBase = blockIdx.y * BN;
    const int b = rowBase >> 12;
    float* gs = blockIdx.y ? g_s1 : g_s0;

    // stage Us (8 x 128 cols of this half) and bn
    float* UsS = (float*)(smem + SM_US);
    float* bnS = (float*)(smem + SM_BNv);
    for (int i = tid; i < MI * BN; i += 256) {
        int m = i >> 7, c = i & 127;
        UsS[i] = u[(m * NB + b) * DQv + colBase + c];
    }
    if (tid < BN) bnS[tid] = bn[colBase + tid];

    // ---- A loader: 128 rows, 2 thr/row, 32 k's each
    const int arow = tid >> 1;
    const int ac0  = (tid & 1) * 32;
    const float* Ap = x + (size_t)(rowBase + arow) * DN + ac0;
    const int aoff  = (arow * A_PADH + ac0) * 2;

    // ---- B loader: 64 k-rows, 4 thr/row, 32 cols each
    const int brow = tid >> 2;
    const int bc0  = (tid & 3) * 32;
    const __half* WHp = g_Whi + (size_t)brow * DQv + colBase + bc0;
    const __half* WLp = g_Wlo + (size_t)brow * DQv + colBase + bc0;
    const int boff  = (brow * B_PADH + bc0) * 2;

    // ldmatrix per-lane base terms
    const uint32_t aHiB = sb + SM_AHI, aLoB = sb + SM_ALO;
    const uint32_t bHiB = sb + SM_BHI, bLoB = sb + SM_BLO;
    const uint32_t arow_l = ((wm * 32 + (lane & 15)) * A_PADH + (lane >> 4) * 8) * 2;
    const uint32_t brow_l = ((lane & 15) * B_PADH + wn * 64 + (lane >> 4) * 8) * 2;

    float    accF[2][8][4];     // main term, fp32
    uint32_t accH[2][8][2];     // corrections, packed fp16
    #pragma unroll
    for (int mt = 0; mt < 2; ++mt)
        #pragma unroll
        for (int nt = 0; nt < 8; ++nt) {
            #pragma unroll
            for (int i = 0; i < 4; ++i) accF[mt][nt][i] = 0.f;
            accH[mt][nt][0] = 0u; accH[mt][nt][1] = 0u;
        }

    float4 fA[8];   // 32 floats staged per thread

    auto issueB = [&](int s, int kt) {
        const __half* ph = WHp + (size_t)kt * BK * DQv;
        const __half* pl = WLp + (size_t)kt * BK * DQv;
        uint32_t dH = bHiB + s * B_STG + boff;
        uint32_t dL = bLoB + s * B_STG + boff;
        #pragma unroll
        for (int j = 0; j < 4; ++j) {
            CPASYNC16(dH + 16 * j, ph + 8 * j);
            CPASYNC16(dL + 16 * j, pl + 8 * j);
        }
        CPASYNC_COMMIT();
    };

    auto loadA = [&](int kt) {
        const float4* p = (const float4*)(Ap + kt * BK);
        #pragma unroll
        for (int j = 0; j < 8; ++j) fA[j] = p[j];
    };

    auto storeA = [&](int s) {
        const float* vf = (const float*)fA;
        uint32_t hw[16], lw[16];
        #pragma unroll
        for (int q = 0; q < 16; ++q) {
            uint32_t hp[2], lp[2];
            #pragma unroll
            for (int e = 0; e < 2; ++e) {
                float w = vf[2 * q + e] * 64.0f;
                __half h = __float2half_rn(w);
                float r = w - __half2float(h);
                __half l = __float2half_rn(r);
                hp[e] = __half_as_ushort(h);
                lp[e] = __half_as_ushort(l);
            }
            hw[q] = hp[0] | (hp[1] << 16);
            lw[q] = lp[0] | (lp[1] << 16);
        }
        char* aH = smem + SM_AHI + s * A_STG + aoff;
        char* aL = smem + SM_ALO + s * A_STG + aoff;
        #pragma unroll
        for (int j = 0; j < 4; ++j) {
            *(uint4*)(aH + 16 * j) = *(uint4*)&hw[4 * j];
            *(uint4*)(aL + 16 * j) = *(uint4*)&lw[4 * j];
        }
    };

    // ---- prologue: stage 0
    issueB(0, 0);
    loadA(0);
    storeA(0);
    CPASYNC_WAIT0();
    __syncthreads();

    #pragma unroll 1
    for (int kt = 0; kt < NSTG; ++kt) {
        const int cur = kt & 1;

        if (kt + 1 < NSTG) {
            issueB(cur ^ 1, kt + 1);
            loadA(kt + 1);
        }

        // compute: 4 x k16 steps
        #pragma unroll
        for (int kk = 0; kk < 4; ++kk) {
            uint32_t ah[2][4], al[2][4];
            #pragma unroll
            for (int mt = 0; mt < 2; ++mt) {
                uint32_t off = arow_l + (uint32_t)((mt * 16 * A_PADH + kk * 16) * 2);
                LDSM4(ah[mt], aHiB + cur * A_STG + off);
                LDSM4(al[mt], aLoB + cur * A_STG + off);
            }
            #pragma unroll
            for (int np = 0; np < 4; ++np) {
                uint32_t off = brow_l + (uint32_t)((kk * 16 * B_PADH + np * 16) * 2);
                uint32_t bh[4], bl[4];
                LDSM4T(bh, bHiB + cur * B_STG + off);
                LDSM4T(bl, bLoB + cur * B_STG + off);
                #pragma unroll
                for (int mt = 0; mt < 2; ++mt) {
                    #pragma unroll
                    for (int st = 0; st < 2; ++st) {
                        MMA16816(accF[mt][np * 2 + st], ah[mt],
                                 bh[2 * st], bh[2 * st + 1]);        // xh*wh
                        MMA16816H(accH[mt][np * 2 + st], ah[mt],
                                  bl[2 * st], bl[2 * st + 1]);       // xh*wl
                        MMA16816H(accH[mt][np * 2 + st], al[mt],
                                  bh[2 * st], bh[2 * st + 1]);       // xl*wh
                    }
                }
            }
        }

        if (kt + 1 < NSTG) storeA(cur ^ 1);
        CPASYNC_WAIT0();
        __syncthreads();
    }

    // ---- epilogue: merge fp16 corrections, scale back, bias, GELU, scores
    const float inv = 1.0f / 32768.0f;     // undo x*64 * W*512
    float p[4][8];
    #pragma unroll
    for (int r = 0; r < 4; ++r)
        #pragma unroll
        for (int m = 0; m < MI; ++m) p[r][m] = 0.f;

    #pragma unroll
    for (int mt = 0; mt < 2; ++mt) {
        #pragma unroll
        for (int nt = 0; nt < 8; ++nt) {
            float corr[4];
            #pragma unroll
            for (int q = 0; q < 2; ++q) {
                float2 c2 = __half22float2(*(__half2*)&accH[mt][nt][q]);
                corr[2 * q]     = c2.x;
                corr[2 * q + 1] = c2.y;
            }
            #pragma unroll
            for (int i = 0; i < 4; ++i) {
                const int col = wn * 64 + nt * 8 + (lane & 3) * 2 + (i & 1);
                float v = (accF[mt][nt][i] + corr[i]) * inv + bnS[col];
                float g = 0.5f * v * (1.0f + erff(v * 0.70710678118654752f));
                const int r = mt * 2 + (i >> 1);
                #pragma unroll
                for (int m = 0; m < MI; ++m)
                    p[r][m] = fmaf(g, UsS[m * BN + col], p[r][m]);
            }
        }
    }

    // reduce across the 4 lanes of each quad (cols partition)
    #pragma unroll
    for (int off = 1; off <= 2; off <<= 1)
        #pragma unroll
        for (int r = 0; r < 4; ++r)
            #pragma unroll
            for (int m = 0; m < MI; ++m)
                p[r][m] += __shfl_xor_sync(0xffffffffu, p[r][m], off);

    // combine the two wn halves via smem (reuse A region; all reads done)
    float* ps = (float*)(smem + SM_AHI);   // [2][128][8]
    if ((lane & 3) == 0) {
        #pragma unroll
        for (int r = 0; r < 4; ++r) {
            const int row = wm * 32 + (r >> 1) * 16 + (lane >> 2) + (r & 1) * 8;
            #pragma unroll
            for (int m = 0; m < MI; ++m)
                ps[(wn * 128 + row) * MI + m] = p[r][m];
        }
    }
    __syncthreads();

    for (int e = tid; e < BM * MI; e += 256) {
        const int row = e >> 3, m = e & 7;
        const int node = (rowBase & (NPG - 1)) + row;
        gs[(b * MI + m) * NPG + node] = ps[row * MI + m] + ps[(128 + row) * MI + m];
    }
}

// ---------------------------------------------------------------------------
// Kernel 2: per graph — softmax, gate, EXACT K-th largest via 4-pass radix
// select on float bits (monotone for non-negative floats), mask = gate >= kth.
// Deterministic: histogram counts are order-independent.
// ---------------------------------------------------------------------------
__global__ void __launch_bounds__(1024)
gate_topk(float* __restrict__ out)
{
    __shared__ float gate[NPG];        // 16 KB
    __shared__ unsigned hist[256];
    __shared__ float red_a[32];
    __shared__ float red_b[32];
    __shared__ unsigned sh_sel, sh_rank;

    const int b = blockIdx.x;
    const int tid = threadIdx.x;
    const int lane = tid & 31, wid = tid >> 5;

    for (int i = tid; i < NPG; i += 1024) gate[i] = 0.f;

    for (int m = 0; m < MI; ++m) {
        const float* s0 = g_s0 + (b * MI + m) * NPG;
        const float* s1 = g_s1 + (b * MI + m) * NPG;
        float v[4];
        float mx = -3.4e38f;
        #pragma unroll
        for (int i = 0; i < 4; ++i) {
            v[i] = s0[(i << 10) + tid] + s1[(i << 10) + tid];
            mx = fmaxf(mx, v[i]);
        }
        #pragma unroll
        for (int off = 16; off > 0; off >>= 1)
            mx = fmaxf(mx, __shfl_xor_sync(0xffffffffu, mx, off));
        if (lane == 0) red_a[wid] = mx;
        __syncthreads();
        mx = red_a[0];
        #pragma unroll
        for (int i = 1; i < 32; ++i) mx = fmaxf(mx, red_a[i]);

        float e[4], se = 0.f;
        #pragma unroll
        for (int i = 0; i < 4; ++i) { e[i] = expf(v[i] - mx); se += e[i]; }
        #pragma unroll
        for (int off = 16; off > 0; off >>= 1)
            se += __shfl_xor_sync(0xffffffffu, se, off);
        if (lane == 0) red_b[wid] = se;
        __syncthreads();
        float tot = 0.f;
        #pragma unroll
        for (int i = 0; i < 32; ++i) tot += red_b[i];

        #pragma unroll
        for (int i = 0; i < 4; ++i)
            gate[(i << 10) + tid] += e[i] / tot;   // per-thread-private slots
        __syncthreads();
    }

    // ---- radix select: exact bit pattern of K-th largest gate value.
    // gates are > 0, so uint bit order == float order.
    unsigned rank = KSEL;
    unsigned prefix = 0;
    #pragma unroll 1
    for (int d = 24; d >= 0; d -= 8) {
        for (int i = tid; i < 256; i += 1024) hist[i] = 0u;
        __syncthreads();
        #pragma unroll
        for (int i = 0; i < 4; ++i) {
            unsigned key = __float_as_uint(gate[(i << 10) + tid]);
            bool match = (d == 24) || ((key >> (d + 8)) == (prefix >> (d + 8)));
            if (match) atomicAdd(&hist[(key >> d) & 255], 1u);
        }
        __syncthreads();
        if (tid == 0) {
            unsigned c = 0;
            unsigned bb = 255;
            for (;; --bb) {
                c += hist[bb];
                if (c >= rank || bb == 0) break;
            }
            sh_sel  = bb;
            sh_rank = rank - (c - hist[bb]);
        }
        __syncthreads();
        prefix |= (sh_sel << d);
        rank = sh_rank;
        __syncthreads();
    }

    const float kth = __uint_as_float(prefix);   // exact K-th largest
    float* o = out + b * NPG;
    for (int i = tid; i < NPG; i += 1024)
        o[i] = (gate[i] >= kth) ? 1.0f : 0.0f;
}

// ---------------------------------------------------------------------------
extern "C" void kernel_launch(void* const* d_in, const int* in_sizes, int n_in,
                              void* d_out, int out_size) {
    const float* x  = (const float*)d_in[0];
    const float* u  = (const float*)d_in[1];
    const float* Wn = (const float*)d_in[2];
    const float* bn = (const float*)d_in[3];
    // d_in[4] = batch (equal sorted segments -> implicit), d_in[5] = edge_index (unused)

    cudaFuncSetAttribute(gemm_hmma,
                         cudaFuncAttributeMaxDynamicSharedMemorySize, SM_DYN);

    convert_w<<<DN * DQv / 256, 256>>>(Wn);
    dim3 grid(NTOT / BM, 2);
    gemm_hmma<<<grid, 256, SM_DYN>>>(x, u, bn);
    gate_topk<<<NB, 1024>>>((float*)d_out);
}

// round 14
// speedup vs baseline: 1.1362x; 1.1362x over previous
#include <cuda_runtime.h>
#include <cuda_fp16.h>
#include <math.h>
#include <stdint.h>

#define DN    512
#define DQv   256
#define NPG   4096
#define NB    64
#define MI    8
#define NTOT  (NB*NPG)
#define KSEL  1229           // ceil(0.3 * 4096)

#define BM   128
#define BN   128
#define BK   32
#define NSTG (DN/BK)         // 16

// ---------------- scratch ----------------
__device__ float g_s0[NB * MI * NPG];     // scores partial, col-half 0 (8 MB)
__device__ float g_s1[NB * MI * NPG];     // col-half 1
__device__ __half g_Whi[DN * DQv];        // W*512 split hi
__device__ __half g_Wlo[DN * DQv];        // W*512 split lo

// ---------------- smem layout (bytes) ----------------
#define A_PAD 40      // halves per A row (32 data + 8 pad)
#define B_PAD 136     // halves per B row (128 data + 8 pad)
#define SM_AHI 0                      // [2][128*40] halves = 20480 B
#define SM_ALO 20480
#define SM_BHI 40960                  // [2][32*136] halves = 17408 B
#define SM_BLO 58368
#define SM_US  75776                  // 8*128 floats = 4096 B
#define SM_BNv 79872                  // 128 floats = 512 B
#define SM_DYN 80384
#define A_STG  10240                  // bytes per A stage
#define B_STG  8704                   // bytes per B stage

__device__ __forceinline__ uint32_t smem_u32(const void* p) {
    uint32_t a;
    asm("{ .reg .u64 t; cvta.to.shared.u64 t, %1; cvt.u32.u64 %0, t; }"
        : "=r"(a) : "l"(p));
    return a;
}

#define LDSM4(r, addr) \
    asm volatile("ldmatrix.sync.aligned.m8n8.x4.shared.b16 {%0,%1,%2,%3}, [%4];" \
        : "=r"((r)[0]), "=r"((r)[1]), "=r"((r)[2]), "=r"((r)[3]) : "r"(addr))

#define LDSM4T(r, addr) \
    asm volatile("ldmatrix.sync.aligned.m8n8.x4.trans.shared.b16 {%0,%1,%2,%3}, [%4];" \
        : "=r"((r)[0]), "=r"((r)[1]), "=r"((r)[2]), "=r"((r)[3]) : "r"(addr))

#define MMA16816(c, a, b0, b1) \
    asm volatile("mma.sync.aligned.m16n8k16.row.col.f32.f16.f16.f32 " \
        "{%0,%1,%2,%3}, {%4,%5,%6,%7}, {%8,%9}, {%0,%1,%2,%3};" \
        : "+f"((c)[0]), "+f"((c)[1]), "+f"((c)[2]), "+f"((c)[3]) \
        : "r"((a)[0]), "r"((a)[1]), "r"((a)[2]), "r"((a)[3]), "r"(b0), "r"(b1))

#define CPASYNC16(dst, src) \
    asm volatile("cp.async.ca.shared.global [%0], [%1], 16;" \
        :: "r"(dst), "l"(src) : "memory")
#define CPASYNC_COMMIT() asm volatile("cp.async.commit_group;" ::: "memory")
#define CPASYNC_WAIT0()  asm volatile("cp.async.wait_group 0;" ::: "memory")

// ---------------------------------------------------------------------------
// Prologue: W [512][256] fp32 -> fp16 Dekker split of W*512 (exact residual)
// ---------------------------------------------------------------------------
__global__ void convert_w(const float* __restrict__ Wn) {
    int idx = blockIdx.x * 256 + threadIdx.x;     // 0..131071
    float w = Wn[idx] * 512.0f;
    __half hi = __float2half_rn(w);
    __half lo = __float2half_rn(w - __half2float(hi));
    g_Whi[idx] = hi;
    g_Wlo[idx] = lo;
}

// ---------------------------------------------------------------------------
// Main: h = gelu((x@Wn)+bn) fused with partial scores over this block's 128
// cols. fp16 2-split, 3-term HMMA, fp32 accum. grid = (2048, 2).
// B tiles stream via cp.async; A converted in registers, double-buffered.
// (Round-10 champion gemm, verbatim.)
// ---------------------------------------------------------------------------
__global__ void __launch_bounds__(256)
gemm_hmma(const float* __restrict__ x, const float* __restrict__ u,
          const float* __restrict__ bn)
{
    extern __shared__ char smem[];
    const uint32_t sb = smem_u32(smem);
    const int tid  = threadIdx.x;
    const int wid  = tid >> 5, lane = tid & 31;
    const int wm   = wid & 3, wn = wid >> 2;     // warp grid 4(M) x 2(N)
    const int rowBase = blockIdx.x * BM;
    const int colBase = blockIdx.y * BN;
    const int b = rowBase >> 12;
    float* gs = blockIdx.y ? g_s1 : g_s0;

    // stage Us (8 x 128 cols of this half) and bn
    float* UsS = (float*)(smem + SM_US);
    float* bnS = (float*)(smem + SM_BNv);
    for (int i = tid; i < MI * BN; i += 256) {
        int m = i >> 7, c = i & 127;
        UsS[i] = u[(m * NB + b) * DQv + colBase + c];
    }
    if (tid < BN) bnS[tid] = bn[colBase + tid];

    // ---- loaders
    const int arow = tid >> 1;                 // 128 rows, 2 thr/row
    const int ac0  = (tid & 1) * 16;           // 16 k's each
    const float* Ap = x + (size_t)(rowBase + arow) * DN + ac0;
    const int aoff  = (arow * A_PAD + ac0) * 2;

    const int brow = tid >> 3;                 // 32 k-rows, 8 thr/row
    const int bc0  = (tid & 7) * 16;           // 16 cols each
    const __half* WHp = g_Whi + (size_t)brow * DQv + colBase + bc0;
    const __half* WLp = g_Wlo + (size_t)brow * DQv + colBase + bc0;
    const int boff  = (brow * B_PAD + bc0) * 2;

    // ldmatrix per-lane base terms
    const uint32_t aHiB = sb + SM_AHI, aLoB = sb + SM_ALO;
    const uint32_t bHiB = sb + SM_BHI, bLoB = sb + SM_BLO;
    const uint32_t arow_l = ((wm * 32 + (lane & 15)) * A_PAD + (lane >> 4) * 8) * 2;
    const uint32_t brow_l = ((lane & 15) * B_PAD + wn * 64 + (lane >> 4) * 8) * 2;

    float acc[2][8][4];
    #pragma unroll
    for (int mt = 0; mt < 2; ++mt)
        #pragma unroll
        for (int nt = 0; nt < 8; ++nt)
            #pragma unroll
            for (int i = 0; i < 4; ++i) acc[mt][nt][i] = 0.f;

    float4 fA[4];

    auto issueB = [&](int s, int kt) {
        const __half* ph = WHp + (size_t)kt * BK * DQv;
        const __half* pl = WLp + (size_t)kt * BK * DQv;
        uint32_t dH = bHiB + s * B_STG + boff;
        uint32_t dL = bLoB + s * B_STG + boff;
        CPASYNC16(dH,      ph);
        CPASYNC16(dH + 16, ph + 8);
        CPASYNC16(dL,      pl);
        CPASYNC16(dL + 16, pl + 8);
        CPASYNC_COMMIT();
    };

    auto storeA = [&](int s) {
        const float* vf = (const float*)fA;
        uint4 hi[2], lo[2];
        uint32_t* hw = (uint32_t*)hi;
        uint32_t* lw = (uint32_t*)lo;
        #pragma unroll
        for (int q = 0; q < 8; ++q) {
            uint32_t hp[2], lp[2];
            #pragma unroll
            for (int e = 0; e < 2; ++e) {
                float w = vf[2 * q + e] * 64.0f;
                __half h = __float2half_rn(w);
                float r = w - __half2float(h);
                __half l = __float2half_rn(r);
                hp[e] = __half_as_ushort(h);
                lp[e] = __half_as_ushort(l);
            }
            hw[q] = hp[0] | (hp[1] << 16);
            lw[q] = lp[0] | (lp[1] << 16);
        }
        char* aH = smem + SM_AHI + s * A_STG + aoff;
        char* aL = smem + SM_ALO + s * A_STG + aoff;
        *(uint4*)(aH)      = hi[0];
        *(uint4*)(aH + 16) = hi[1];
        *(uint4*)(aL)      = lo[0];
        *(uint4*)(aL + 16) = lo[1];
    };

    // ---- prologue: stage 0
    issueB(0, 0);
    {
        const float4* p = (const float4*)Ap;
        fA[0] = p[0]; fA[1] = p[1]; fA[2] = p[2]; fA[3] = p[3];
    }
    storeA(0);
    CPASYNC_WAIT0();
    __syncthreads();

    for (int kt = 0; kt < NSTG; ++kt) {
        const int cur = kt & 1;

        // kick off next stage's B copies and A register loads BEFORE compute
        if (kt + 1 < NSTG) {
            issueB(cur ^ 1, kt + 1);
            const float4* p = (const float4*)(Ap + (kt + 1) * BK);
            fA[0] = p[0]; fA[1] = p[1]; fA[2] = p[2]; fA[3] = p[3];
        }

        // compute: 2 x k16 steps
        #pragma unroll
        for (int kk = 0; kk < 2; ++kk) {
            uint32_t ah[2][4], al[2][4];
            #pragma unroll
            for (int mt = 0; mt < 2; ++mt) {
                uint32_t off = arow_l + (uint32_t)((mt * 16 * A_PAD + kk * 16) * 2);
                LDSM4(ah[mt], aHiB + cur * A_STG + off);
                LDSM4(al[mt], aLoB + cur * A_STG + off);
            }
            #pragma unroll
            for (int np = 0; np < 4; ++np) {
                uint32_t off = brow_l + (uint32_t)((kk * 16 * B_PAD + np * 16) * 2);
                uint32_t bh[4], bl[4];
                LDSM4T(bh, bHiB + cur * B_STG + off);
                LDSM4T(bl, bLoB + cur * B_STG + off);
                #pragma unroll
                for (int mt = 0; mt < 2; ++mt) {
                    #pragma unroll
                    for (int st = 0; st < 2; ++st) {
                        float* c = acc[mt][np * 2 + st];
                        MMA16816(c, ah[mt], bh[2 * st], bh[2 * st + 1]);
                        MMA16816(c, ah[mt], bl[2 * st], bl[2 * st + 1]);
                        MMA16816(c, al[mt], bh[2 * st], bh[2 * st + 1]);
                    }
                }
            }
        }

        if (kt + 1 < NSTG) storeA(cur ^ 1);
        CPASYNC_WAIT0();
        __syncthreads();
    }

    // ---- epilogue: scale back, bias, exact GELU, partial score dots
    const float inv = 1.0f / 32768.0f;     // undo x*64 * W*512
    float p[4][8];
    #pragma unroll
    for (int r = 0; r < 4; ++r)
        #pragma unroll
        for (int m = 0; m < MI; ++m) p[r][m] = 0.f;

    #pragma unroll
    for (int mt = 0; mt < 2; ++mt) {
        #pragma unroll
        for (int nt = 0; nt < 8; ++nt) {
            #pragma unroll
            for (int i = 0; i < 4; ++i) {
                const int col = wn * 64 + nt * 8 + (lane & 3) * 2 + (i & 1);
                float v = acc[mt][nt][i] * inv + bnS[col];
                float g = 0.5f * v * (1.0f + erff(v * 0.70710678118654752f));
                const int r = mt * 2 + (i >> 1);
                #pragma unroll
                for (int m = 0; m < MI; ++m)
                    p[r][m] = fmaf(g, UsS[m * BN + col], p[r][m]);
            }
        }
    }

    // reduce across the 4 lanes of each quad (cols partition)
    #pragma unroll
    for (int off = 1; off <= 2; off <<= 1)
        #pragma unroll
        for (int r = 0; r < 4; ++r)
            #pragma unroll
            for (int m = 0; m < MI; ++m)
                p[r][m] += __shfl_xor_sync(0xffffffffu, p[r][m], off);

    // combine the two wn halves via smem (reuse A region; all reads done)
    float* ps = (float*)(smem + SM_AHI);   // [2][128][8] floats = 8 KB
    if ((lane & 3) == 0) {
        #pragma unroll
        for (int r = 0; r < 4; ++r) {
            const int row = wm * 32 + (r >> 1) * 16 + (lane >> 2) + (r & 1) * 8;
            #pragma unroll
            for (int m = 0; m < MI; ++m)
                ps[(wn * 128 + row) * MI + m] = p[r][m];
        }
    }
    __syncthreads();

    for (int e = tid; e < BM * MI; e += 256) {
        const int row = e >> 3, m = e & 7;
        const int node = (rowBase & (NPG - 1)) + row;
        gs[(b * MI + m) * NPG + node] = ps[row * MI + m] + ps[(128 + row) * MI + m];
    }
}

// ---------------------------------------------------------------------------
// Kernel 2: per graph — softmax, gate, EXACT K-th largest via 4-pass radix
// select on float bits (monotone for positive floats), mask = gate >= kth.
// Deterministic: histogram counts are order-independent. (Round-13 validated.)
// ---------------------------------------------------------------------------
__global__ void __launch_bounds__(1024)
gate_topk(float* __restrict__ out)
{
    __shared__ float gate[NPG];        // 16 KB
    __shared__ unsigned hist[256];
    __shared__ float red_a[32];
    __shared__ float red_b[32];
    __shared__ unsigned sh_sel, sh_rank;

    const int b = blockIdx.x;
    const int tid = threadIdx.x;
    const int lane = tid & 31, wid = tid >> 5;

    for (int i = tid; i < NPG; i += 1024) gate[i] = 0.f;

    for (int m = 0; m < MI; ++m) {
        const float* s0 = g_s0 + (b * MI + m) * NPG;
        const float* s1 = g_s1 + (b * MI + m) * NPG;
        float v[4];
        float mx = -3.4e38f;
        #pragma unroll
        for (int i = 0; i < 4; ++i) {
            v[i] = s0[(i << 10) + tid] + s1[(i << 10) + tid];
            mx = fmaxf(mx, v[i]);
        }
        #pragma unroll
        for (int off = 16; off > 0; off >>= 1)
            mx = fmaxf(mx, __shfl_xor_sync(0xffffffffu, mx, off));
        if (lane == 0) red_a[wid] = mx;
        __syncthreads();
        mx = red_a[0];
        #pragma unroll
        for (int i = 1; i < 32; ++i) mx = fmaxf(mx, red_a[i]);

        float e[4], se = 0.f;
        #pragma unroll
        for (int i = 0; i < 4; ++i) { e[i] = expf(v[i] - mx); se += e[i]; }
        #pragma unroll
        for (int off = 16; off > 0; off >>= 1)
            se += __shfl_xor_sync(0xffffffffu, se, off);
        if (lane == 0) red_b[wid] = se;
        __syncthreads();
        float tot = 0.f;
        #pragma unroll
        for (int i = 0; i < 32; ++i) tot += red_b[i];

        #pragma unroll
        for (int i = 0; i < 4; ++i)
            gate[(i << 10) + tid] += e[i] / tot;   // per-thread-private slots
        __syncthreads();
    }

    // ---- radix select: exact bit pattern of K-th largest gate value.
    // gates are > 0, so uint bit order == float order.
    unsigned rank = KSEL;
    unsigned prefix = 0;
    #pragma unroll 1
    for (int d = 24; d >= 0; d -= 8) {
        for (int i = tid; i < 256; i += 1024) hist[i] = 0u;
        __syncthreads();
        #pragma unroll
        for (int i = 0; i < 4; ++i) {
            unsigned key = __float_as_uint(gate[(i << 10) + tid]);
            bool match = (d == 24) || ((key >> (d + 8)) == (prefix >> (d + 8)));
            if (match) atomicAdd(&hist[(key >> d) & 255], 1u);
        }
        __syncthreads();
        if (tid == 0) {
            unsigned c = 0;
            unsigned bb = 255;
            for (;; --bb) {
                c += hist[bb];
                if (c >= rank || bb == 0) break;
            }
            sh_sel  = bb;
            sh_rank = rank - (c - hist[bb]);
        }
        __syncthreads();
        prefix |= (sh_sel << d);
        rank = sh_rank;
        __syncthreads();
    }

    const float kth = __uint_as_float(prefix);   // exact K-th largest
    float* o = out + b * NPG;
    for (int i = tid; i < NPG; i += 1024)
        o[i] = (gate[i] >= kth) ? 1.0f : 0.0f;
}

// ---------------------------------------------------------------------------
extern "C" void kernel_launch(void* const* d_in, const int* in_sizes, int n_in,
                              void* d_out, int out_size) {
    const float* x  = (const float*)d_in[0];
    const float* u  = (const float*)d_in[1];
    const float* Wn = (const float*)d_in[2];
    const float* bn = (const float*)d_in[3];
    // d_in[4] = batch (equal sorted segments -> implicit), d_in[5] = edge_index (unused)

    cudaFuncSetAttribute(gemm_hmma,
                         cudaFuncAttributeMaxDynamicSharedMemorySize, SM_DYN);

    convert_w<<<DN * DQv / 256, 256>>>(Wn);
    dim3 grid(NTOT / BM, 2);
    gemm_hmma<<<grid, 256, SM_DYN>>>(x, u, bn);
    gate_topk<<<NB, 1024>>>((float*)d_out);
}